// round 1
// baseline (speedup 1.0000x reference)
#include <cuda_runtime.h>
#include <math.h>

// Problem constants (N=128 images, P=16 control points, S=128 grid)
#define NIMG 128
#define NP   16
#define SDIM 128
#define RAD  6
#define KW   (2*RAD+1)        // 13-tap Gaussian (exp(-36) ~ 2e-16, negligible)

// Shared layouts
#define ROWC (129 + 2*RAD)    // 141 histogram rows (x in 0..128, +halo)
#define COLC 132              // histogram cols padded (y in 0..128)
#define ROWM 128              // M1 rows (s)
#define COLM 144              // M1 cols padded (y+halo: need 141)

#define SMEM_FLOATS (ROWC*COLC + ROWM*COLM)

__global__ __launch_bounds__(256)
void plotline2_kernel(const float* __restrict__ points, float* __restrict__ out)
{
    extern __shared__ float sm[];
    float* cnt = sm;                    // [ROWC][COLC]
    float* m1  = sm + ROWC * COLC;      // [ROWM][COLM]

    const int n   = blockIdx.x;
    const int tid = threadIdx.x;

    // Gaussian taps: w[d'] = exp(-(d'-RAD)^2)
    float w[KW];
#pragma unroll
    for (int d = 0; d < KW; ++d) {
        int dd = d - RAD;
        w[d] = expf(-(float)(dd * dd));
    }

    // ---- zero shared ----
    for (int i = tid; i < SMEM_FLOATS; i += 256) sm[i] = 0.0f;
    __syncthreads();

    // ---- stage 1: histogram of rounded interpolated points ----
    // K = (P-1)*S = 1920 points: seg = k/128, step i = k%128, t = i/128
    const float inv = 1.0f / (float)SDIM;
    const float* pn = points + n * NP * 2;
    for (int k = tid; k < (NP - 1) * SDIM; k += 256) {
        int seg = k >> 7;
        int i   = k & 127;
        float t   = (float)i * inv;        // exact (i/128)
        float omt = 1.0f - t;              // exact
        float x0 = pn[seg * 2 + 0];
        float y0 = pn[seg * 2 + 1];
        float x1 = pn[seg * 2 + 2];
        float y1 = pn[seg * 2 + 3];
        // match XLA: mul, mul, add — no fma contraction
        float x = __fadd_rn(__fmul_rn(omt, x0), __fmul_rn(t, x1));
        float y = __fadd_rn(__fmul_rn(omt, y0), __fmul_rn(t, y1));
        int ix = (int)rintf(x);            // round-half-to-even, 0..128
        int iy = (int)rintf(y);
        atomicAdd(&cnt[(ix + RAD) * COLC + iy], 1.0f);
    }
    __syncthreads();

    // ---- stage 2: vertical (x) convolution ----
    // m1[s][y] = sum_{d'} w[d'] * cnt[s + d'][y],  s in 0..127, y in 0..128
    // 8-wide sliding window along s per thread: 20 loads -> 8 outputs
    for (int item = tid; item < 16 * 129; item += 256) {
        int sg = item / 129;               // s-group (0..15)
        int y  = item - sg * 129;          // 0..128
        int sbase = sg * 8;
        float v[8 + KW - 1];               // 20
#pragma unroll
        for (int j = 0; j < 8 + KW - 1; ++j)
            v[j] = cnt[(sbase + j) * COLC + y];
#pragma unroll
        for (int i = 0; i < 8; ++i) {
            float acc = 0.0f;
#pragma unroll
            for (int d = 0; d < KW; ++d)
                acc = fmaf(w[d], v[i + d], acc);
            m1[(sbase + i) * COLM + (y + RAD)] = acc;
        }
    }
    __syncthreads();

    // ---- stage 3: horizontal (y) convolution + tanh + store ----
    // out[s][t] = tanh( sum_{d'} w[d'] * m1[s][t + d'] )
    float* outn = out + (size_t)n * SDIM * SDIM;
    for (int item = tid; item < SDIM * 16; item += 256) {
        int s  = item >> 4;
        int tb = (item & 15) * 8;
        float v[8 + KW - 1];
#pragma unroll
        for (int j = 0; j < 8 + KW - 1; ++j)
            v[j] = m1[s * COLM + tb + j];
        float r[8];
#pragma unroll
        for (int i = 0; i < 8; ++i) {
            float acc = 0.0f;
#pragma unroll
            for (int d = 0; d < KW; ++d)
                acc = fmaf(w[d], v[i + d], acc);
            r[i] = tanhf(acc);
        }
        // vectorized store: 2x float4 per thread
        float4* dst = (float4*)(outn + s * SDIM + tb);
        dst[0] = make_float4(r[0], r[1], r[2], r[3]);
        dst[1] = make_float4(r[4], r[5], r[6], r[7]);
    }
}

extern "C" void kernel_launch(void* const* d_in, const int* in_sizes, int n_in,
                              void* d_out, int out_size)
{
    const float* points = (const float*)d_in[0];
    float* out = (float*)d_out;

    size_t smem = SMEM_FLOATS * sizeof(float);   // ~148 KB
    cudaFuncSetAttribute(plotline2_kernel,
                         cudaFuncAttributeMaxDynamicSharedMemorySize, (int)smem);
    plotline2_kernel<<<NIMG, 256, smem>>>(points, out);
}